// round 7
// baseline (speedup 1.0000x reference)
#include <cuda_runtime.h>
#include <cuda_bf16.h>
#include <cstdint>

// CapLayer — exact routing collapse (b0==0; softmax over the caps axis keeps
// coefficients uniform at 1/10 in every routing iteration):
//   U[b,s,k] = sum_{n<144} x[b][s*1152 + n*8 + k]
//   S[b,d]   = 0.1*( sum_{s,k} U[b,s,k]*W[s,d,k] + 144*sum_s Wb[s,d] )
//   out[b,o,d] = S[b,d] * ||S|| / (1 + ||S||^2)   replicated over o=0..9
//
// LDG loading is register-MLP-capped (~5.6 TB/s). This version streams x via
// cp.async.bulk (UBLKCP) into a 2-stage x 36KB smem ring — the async engine
// holds the in-flight bytes, so the chip runs at the LTS cap instead. Warps
// reduce each chunk from smem with conflict-free LDS.128 + parity shfl.

#define NUM_SHARED 32
#define IN_DIM 8
#define OUT_DIM 16
#define NUM_OUT 10
#define HW 144
#define X_PER_B (NUM_SHARED * HW * IN_DIM)   // 36864 floats = 147456 B
#define BS 512

#define CHUNK_BYTES 36864      // 8 s-groups
#define CHUNK_F4    (CHUNK_BYTES / 16)
#define NCHUNK      4
#define NSTAGE      2
#define DSMEM_BYTES (NSTAGE * CHUNK_BYTES)   // 73728

__device__ __forceinline__ uint32_t smem_u32(const void* p) {
    uint32_t a;
    asm("{ .reg .u64 t; cvta.to.shared.u64 t, %1; cvt.u32.u64 %0, t; }"
        : "=r"(a) : "l"(p));
    return a;
}

__device__ __forceinline__ void mbar_init(uint32_t mb, uint32_t cnt) {
    asm volatile("mbarrier.init.shared.b64 [%0], %1;" :: "r"(mb), "r"(cnt) : "memory");
}
__device__ __forceinline__ void mbar_expect_tx(uint32_t mb, uint32_t bytes) {
    asm volatile("mbarrier.arrive.expect_tx.shared.b64 _, [%0], %1;"
                 :: "r"(mb), "r"(bytes) : "memory");
}
__device__ __forceinline__ void mbar_wait(uint32_t mb, uint32_t ph) {
    uint32_t done;
    asm volatile(
        "{\n\t.reg .pred p;\n\t"
        "mbarrier.try_wait.parity.acquire.cta.shared::cta.b64 p, [%1], %2;\n\t"
        "selp.b32 %0, 1, 0, p;\n\t}"
        : "=r"(done) : "r"(mb), "r"(ph) : "memory");
    while (!done) {
        asm volatile(
            "{\n\t.reg .pred p;\n\t"
            "mbarrier.try_wait.parity.acquire.cta.shared::cta.b64 p, [%1], %2, 0x989680;\n\t"
            "selp.b32 %0, 1, 0, p;\n\t}"
            : "=r"(done) : "r"(mb), "r"(ph) : "memory");
    }
}
__device__ __forceinline__ void bulk_g2s(uint32_t dst, const void* src,
                                         uint32_t bytes, uint32_t mb) {
    asm volatile(
        "cp.async.bulk.shared::cluster.global.mbarrier::complete_tx::bytes "
        "[%0], [%1], %2, [%3];"
        :: "r"(dst), "l"(src), "r"(bytes), "r"(mb) : "memory");
}

extern __shared__ __align__(16) unsigned char dynsmem[];

__global__ __launch_bounds__(256)
void caplayer_kernel(const float* __restrict__ x,
                     const float* __restrict__ W,
                     const float* __restrict__ Wb,
                     float* __restrict__ out)
{
    __shared__ __align__(8) unsigned long long mbar_store[NSTAGE];
    __shared__ float U[NUM_SHARED * IN_DIM];
    __shared__ float Sd[OUT_DIM];
    __shared__ float coeff_sh;

    const int b    = blockIdx.x;
    const int t    = threadIdx.x;
    const int w    = t >> 5;      // warp 0..7
    const int lane = t & 31;

    const uint32_t mb0 = smem_u32(&mbar_store[0]);
    const uint32_t sm0 = smem_u32(dynsmem);
    const char* src = (const char*)(x + (size_t)b * X_PER_B);

    if (t == 0) {
        mbar_init(mb0, 1);
        mbar_init(mb0 + 8, 1);
    }
    __syncthreads();

    // Prologue: fill both stages.
    if (t == 0) {
        mbar_expect_tx(mb0, CHUNK_BYTES);
        bulk_g2s(sm0, src, CHUNK_BYTES, mb0);
        mbar_expect_tx(mb0 + 8, CHUNK_BYTES);
        bulk_g2s(sm0 + CHUNK_BYTES, src + CHUNK_BYTES, CHUNK_BYTES, mb0 + 8);
    }

    // Main loop: chunk c = s-groups [c*8, c*8+8). Warp w owns group c*8+w:
    // float4 indices w*288 + r*32 + lane, r=0..8 (conflict-free LDS.128).
    // Lane parity == k-half; parity-preserving shfl finishes the n-sum.
    #pragma unroll
    for (int c = 0; c < NCHUNK; c++) {
        const int      st = c & 1;
        const uint32_t ph = (c >> 1) & 1;
        mbar_wait(mb0 + st * 8, ph);

        const float4* buf = (const float4*)(dynsmem + st * CHUNK_BYTES);
        float4 acc = make_float4(0.f, 0.f, 0.f, 0.f);
        const int base = w * 288 + lane;
        #pragma unroll
        for (int r = 0; r < 9; r++) {
            float4 v = buf[base + r * 32];
            acc.x += v.x; acc.y += v.y; acc.z += v.z; acc.w += v.w;
        }
        #pragma unroll
        for (int m = 2; m < 32; m <<= 1) {
            acc.x += __shfl_xor_sync(0xFFFFFFFFu, acc.x, m);
            acc.y += __shfl_xor_sync(0xFFFFFFFFu, acc.y, m);
            acc.z += __shfl_xor_sync(0xFFFFFFFFu, acc.z, m);
            acc.w += __shfl_xor_sync(0xFFFFFFFFu, acc.w, m);
        }
        if (lane < 2) {   // lane 0 -> k 0..3, lane 1 -> k 4..7
            *(float4*)&U[(c * 8 + w) * IN_DIM + lane * 4] = acc;
        }
        __syncthreads();   // stage st fully consumed (and U visible)

        if (t == 0 && c + NSTAGE < NCHUNK) {
            const int nc = c + NSTAGE;
            mbar_expect_tx(mb0 + st * 8, CHUNK_BYTES);
            bulk_g2s(sm0 + st * CHUNK_BYTES, src + (size_t)nc * CHUNK_BYTES,
                     CHUNK_BYTES, mb0 + st * 8);
        }
    }

    // Tiny GEMV: S[d] = 0.1*( sum_{s,k} U*W + 144*sum_s Wb )
    if (t < OUT_DIM) {
        const int d = t;
        float a0 = 0.f, a1 = 0.f;
        #pragma unroll
        for (int s2 = 0; s2 < NUM_SHARED; s2 += 2) {
            a0 += 144.f * Wb[s2 * OUT_DIM + d];
            a1 += 144.f * Wb[(s2 + 1) * OUT_DIM + d];
            #pragma unroll
            for (int k2 = 0; k2 < IN_DIM; k2++) {
                a0 += U[s2 * IN_DIM + k2]       * W[(s2 * OUT_DIM + d) * IN_DIM + k2];
                a1 += U[(s2 + 1) * IN_DIM + k2] * W[((s2 + 1) * OUT_DIM + d) * IN_DIM + k2];
            }
        }
        Sd[d] = 0.1f * (a0 + a1);
    }
    __syncthreads();

    if (t == 0) {
        float n2 = 0.f;
        #pragma unroll
        for (int d = 0; d < OUT_DIM; d++) n2 += Sd[d] * Sd[d];
        coeff_sh = sqrtf(n2) / (1.f + n2);
    }
    __syncthreads();

    if (t < NUM_OUT * OUT_DIM) {
        out[(size_t)b * (NUM_OUT * OUT_DIM) + t] = Sd[t & (OUT_DIM - 1)] * coeff_sh;
    }
}

extern "C" void kernel_launch(void* const* d_in, const int* in_sizes, int n_in,
                              void* d_out, int out_size)
{
    const float* x  = (const float*)d_in[0];
    const float* W  = (const float*)d_in[1];
    const float* Wb = (const float*)d_in[2];
    // d_in[3] = b0 (zeros) — unused after the routing collapse.
    float* out = (float*)d_out;

    cudaFuncSetAttribute(caplayer_kernel,
                         cudaFuncAttributeMaxDynamicSharedMemorySize, DSMEM_BYTES);
    caplayer_kernel<<<BS, 256, DSMEM_BYTES>>>(x, W, Wb, out);
}

// round 8
// speedup vs baseline: 1.3933x; 1.3933x over previous
#include <cuda_runtime.h>
#include <cuda_bf16.h>
#include <cstdint>

// CapLayer — exact routing collapse (b0==0; softmax over the caps axis keeps
// coefficients uniform at 1/10 in every routing iteration):
//   U[b,s,k] = sum_{n<144} x[b][s*1152 + n*8 + k]
//   S[b,d]   = 0.1*( sum_{s,k} U[b,s,k]*W[s,d,k] + 144*sum_s Wb[s,d] )
//   out[b,o,d] = S[b,d] * ||S|| / (1 + ||S||^2)   replicated over o=0..9
//
// Cluster-2 layout: 1024 CTAs (= 512 clusters = 512 batches) x 128 threads,
// <=64 regs -> 8 CTA/SM -> the whole grid is resident in ONE wave (1184 slots)
// and per-SM load imbalance drops to ~1.2% (vs 15.6% for 512x256).
// Rank r reduces s-groups [16r,16r+16) with fully-coalesced LDG.128 + parity
// shfl, computes a 16-float partial S, and the halves join through DSMEM
// (mapa + st.shared::cluster + one cluster barrier) — no gpu-scope fences,
// no atomics, bitwise-deterministic.

#define NUM_SHARED 32
#define IN_DIM 8
#define OUT_DIM 16
#define NUM_OUT 10
#define HW 144
#define X_PER_B (NUM_SHARED * HW * IN_DIM)   // 36864 floats
#define BS 512

__device__ __forceinline__ uint32_t smem_u32(const void* p) {
    uint32_t a;
    asm("{ .reg .u64 t; cvta.to.shared.u64 t, %1; cvt.u32.u64 %0, t; }"
        : "=r"(a) : "l"(p));
    return a;
}

__global__ __launch_bounds__(128, 8) __cluster_dims__(2, 1, 1)
void caplayer_kernel(const float* __restrict__ x,
                     const float* __restrict__ W,
                     const float* __restrict__ Wb,
                     float* __restrict__ out)
{
    __shared__ float U[16 * IN_DIM];      // this rank's 16 groups x 8 k
    __shared__ float Spart[2][OUT_DIM];   // partials, gathered in rank 0
    __shared__ float Sd[OUT_DIM];
    __shared__ float coeff_sh;

    const int cta  = blockIdx.x;
    const int b    = cta >> 1;
    const int rank = cta & 1;             // == %cluster_ctarank for (2,1,1)
    const int s0   = rank * 16;
    const int t    = threadIdx.x;
    const int w    = t >> 5;              // warp 0..3 -> groups s0 + 4w .. +3
    const int lane = t & 31;

    // ---- Phase 1: 36 fully-coalesced LDG.128 per thread over this half of x.
    // Group g owns float4 indices [g*288,(g+1)*288); 288 = 9 warp-chunks of 32.
    // Lane parity == k-half, so chunk sums accumulate over n only.
    const float4* xb = (const float4*)(x + (size_t)b * X_PER_B) + s0 * 288;

    float4 acc[4];
    #pragma unroll
    for (int si = 0; si < 4; si++) acc[si] = make_float4(0.f, 0.f, 0.f, 0.f);

    const int base = (w * 4) * 288 + lane;
    #pragma unroll
    for (int si = 0; si < 4; si++) {
        #pragma unroll
        for (int c = 0; c < 9; c++) {
            float4 v = xb[base + si * 288 + c * 32];
            acc[si].x += v.x; acc[si].y += v.y;
            acc[si].z += v.z; acc[si].w += v.w;
        }
    }

    // ---- Phase 2: parity-preserving warp reduction (finishes the n-sum).
    #pragma unroll
    for (int si = 0; si < 4; si++) {
        #pragma unroll
        for (int m = 2; m < 32; m <<= 1) {
            acc[si].x += __shfl_xor_sync(0xFFFFFFFFu, acc[si].x, m);
            acc[si].y += __shfl_xor_sync(0xFFFFFFFFu, acc[si].y, m);
            acc[si].z += __shfl_xor_sync(0xFFFFFFFFu, acc[si].z, m);
            acc[si].w += __shfl_xor_sync(0xFFFFFFFFu, acc[si].w, m);
        }
        if (lane < 2) {   // lane 0 -> k 0..3, lane 1 -> k 4..7
            *(float4*)&U[(w * 4 + si) * IN_DIM + lane * 4] = acc[si];
        }
    }
    __syncthreads();

    // ---- Phase 3: partial GEMV over this rank's 16 groups (no bias, no 0.1).
    if (t < OUT_DIM) {
        const int d = t;
        float a0 = 0.f, a1 = 0.f;
        #pragma unroll
        for (int j = 0; j < 16; j += 2) {
            #pragma unroll
            for (int k2 = 0; k2 < IN_DIM; k2++) {
                a0 += U[j * IN_DIM + k2]       * W[((s0 + j) * OUT_DIM + d) * IN_DIM + k2];
                a1 += U[(j + 1) * IN_DIM + k2] * W[((s0 + j + 1) * OUT_DIM + d) * IN_DIM + k2];
            }
        }
        float p = a0 + a1;
        if (rank == 0) {
            Spart[0][d] = p;
        } else {
            // Push partial into rank 0's Spart[1][d] via DSMEM.
            uint32_t laddr = smem_u32(&Spart[1][d]);
            uint32_t raddr;
            asm volatile("mapa.shared::cluster.u32 %0, %1, %2;"
                         : "=r"(raddr) : "r"(laddr), "r"(0));
            asm volatile("st.shared::cluster.f32 [%0], %1;"
                         :: "r"(raddr), "f"(p) : "memory");
        }
    }

    // ---- Phase 4: cluster join (release on arrive, acquire on wait).
    asm volatile("barrier.cluster.arrive.aligned;" ::: "memory");
    asm volatile("barrier.cluster.wait.aligned;" ::: "memory");
    if (rank != 0) return;

    if (t < OUT_DIM) {
        float p = Spart[0][t] + Spart[1][t];
        float bias = 0.f;
        #pragma unroll
        for (int s2 = 0; s2 < NUM_SHARED; s2++) bias += Wb[s2 * OUT_DIM + t];
        Sd[t] = 0.1f * (p + 144.f * bias);
    }
    __syncthreads();

    if (t == 0) {
        float n2 = 0.f;
        #pragma unroll
        for (int d = 0; d < OUT_DIM; d++) n2 += Sd[d] * Sd[d];
        coeff_sh = sqrtf(n2) / (1.f + n2);
    }
    __syncthreads();

    const float c = coeff_sh;
    float* ob = out + (size_t)b * (NUM_OUT * OUT_DIM);
    #pragma unroll
    for (int i = t; i < NUM_OUT * OUT_DIM; i += 128) {
        ob[i] = Sd[i & (OUT_DIM - 1)] * c;
    }
}

extern "C" void kernel_launch(void* const* d_in, const int* in_sizes, int n_in,
                              void* d_out, int out_size)
{
    const float* x  = (const float*)d_in[0];
    const float* W  = (const float*)d_in[1];
    const float* Wb = (const float*)d_in[2];
    // d_in[3] = b0 (zeros) — unused after the routing collapse.
    float* out = (float*)d_out;

    caplayer_kernel<<<BS * 2, 128>>>(x, W, Wb, out);
}